// round 1
// baseline (speedup 1.0000x reference)
#include <cuda_runtime.h>

// ---------------- scratch (device globals; no allocations allowed) ----------------
__device__ float g_h1[46099200];   // (128,150,49,49)
__device__ float g_h2[46099200];   // (128,150,49,49)
__device__ float g_sT[23970816];   // (128,51*51,72)  trans -> softmax in-place
__device__ float g_rew[332928];    // (128,51*51)
__device__ float g_q[2458624];     // (128,49,49,8)

// ---------------- f32x2 helpers ----------------
__device__ __forceinline__ unsigned long long dup_f32x2(float v) {
    unsigned long long r;
    unsigned int u = __float_as_uint(v);
    asm("mov.b64 %0, {%1, %2};" : "=l"(r) : "r"(u), "r"(u));
    return r;
}
#define FMA2(d, a, b) asm("fma.rn.f32x2 %0, %1, %2, %0;" : "+l"(d) : "l"(a), "l"(b))

// ---------------- generic 3x3 conv (input 49x49 NCHW) ----------------
// EPI=0: NCHW output (+bias, +relu).  EPI=1: pixel-major (b, y*51+x, oc) output, no bias/relu.
// Thread tile: 8 x-pixels x TOC out-channels (as TOC/2 f32x2 pairs). CTA: 6 rows x 7 x-groups x (OCT/TOC) oc-subgroups.
template<int IC, int PAD, bool RELU, int OCT, int TOC, int EPI>
__global__ void __launch_bounds__((OCT / TOC) * 42)
conv3x3_kernel(const float* __restrict__ in, const float* __restrict__ w,
               const float* __restrict__ bias, float* __restrict__ out, const int OC)
{
    constexpr int HW  = 47 + 2 * PAD;   // 49 (pad1) or 51 (pad2)
    constexpr int SUB = OCT / TOC;
    constexpr int NT  = SUB * 7 * 6;
    constexpr int NP  = TOC / 2;

    const int tid = threadIdx.x;
    const int ts  = tid % SUB;            // oc subgroup (fast -> smem x reads broadcast)
    const int tx  = (tid / SUB) % 7;      // x group (8 px each)
    const int ty  = tid / (SUB * 7);      // row within tile

    const int y0  = blockIdx.x * 6;
    const int oc0 = blockIdx.y * OCT;
    const int b   = blockIdx.z;

    __shared__ __align__(16) float xs[8][64];
    __shared__ __align__(16) float ws[9][OCT];

    unsigned long long acc[8][NP];
#pragma unroll
    for (int i = 0; i < 8; ++i)
#pragma unroll
        for (int p = 0; p < NP; ++p) acc[i][p] = 0ull;

    const int ocb = ts * TOC;
    const int txb = tx * 8;
    const float* inb = in + (size_t)b * IC * 2401;

    for (int c = 0; c < IC; ++c) {
        __syncthreads();
        // stage input tile (rows y0-PAD .. y0-PAD+7, cols -PAD.., zero-filled OOB)
        for (int i = tid; i < 512; i += NT) {
            const int r = i >> 6, col = i & 63;
            const int iy = y0 - PAD + r;
            const int ix = col - PAD;
            float v = 0.f;
            if (iy >= 0 && iy < 49 && ix >= 0 && ix < 49)
                v = inb[(c * 49 + iy) * 49 + ix];
            xs[r][col] = v;
        }
        // stage weights as [k][oc_local] so oc-pairs are contiguous (LDS.64)
        for (int i = tid; i < OCT * 9; i += NT) {
            const int ocl = i / 9, k = i - ocl * 9;
            const int oc  = oc0 + ocl;
            ws[k][ocl] = (oc < OC) ? w[((size_t)oc * IC + c) * 9 + k] : 0.f;
        }
        __syncthreads();

        // duplicate the 3x10 activation neighborhood into {v,v} packs once
        unsigned long long xd[3][10];
#pragma unroll
        for (int ky = 0; ky < 3; ++ky)
#pragma unroll
            for (int cc = 0; cc < 10; ++cc)
                xd[ky][cc] = dup_f32x2(xs[ty + ky][txb + cc]);

#pragma unroll
        for (int ky = 0; ky < 3; ++ky)
#pragma unroll
        for (int kx = 0; kx < 3; ++kx) {
            const int k = ky * 3 + kx;
            unsigned long long wp[NP];
#pragma unroll
            for (int p = 0; p < NP; ++p)
                wp[p] = *reinterpret_cast<const unsigned long long*>(&ws[k][ocb + 2 * p]);
#pragma unroll
            for (int px = 0; px < 8; ++px)
#pragma unroll
                for (int p = 0; p < NP; ++p)
                    FMA2(acc[px][p], wp[p], xd[ky][px + kx]);
        }
    }

    const int y = y0 + ty;
    if (y >= HW) return;
#pragma unroll
    for (int px = 0; px < 8; ++px) {
        const int x = txb + px;
        if (x >= HW) continue;
#pragma unroll
        for (int p = 0; p < NP; ++p) {
            unsigned int ulo, uhi;
            asm("mov.b64 {%0, %1}, %2;" : "=r"(ulo), "=r"(uhi) : "l"(acc[px][p]));
            float v2[2] = { __uint_as_float(ulo), __uint_as_float(uhi) };
#pragma unroll
            for (int j = 0; j < 2; ++j) {
                const int oc = oc0 + ocb + 2 * p + j;
                if (oc >= OC) continue;
                float v = v2[j];
                if (EPI == 0) {
                    if (bias) v += bias[oc];
                    if (RELU) v = fmaxf(v, 0.f);
                    out[((size_t)(b * OC + oc) * HW + y) * HW + x] = v;
                } else {
                    out[((size_t)b * 2601 + y * 51 + x) * 72 + oc] = v;
                }
            }
        }
    }
}

// ---------------- reward conv: 150->1, pad=2, out (B,51,51) ----------------
__global__ void reward_kernel(const float* __restrict__ h2, const float* __restrict__ rw,
                              float* __restrict__ rewout)
{
    __shared__ float wsm[1350];
    for (int i = threadIdx.x; i < 1350; i += 256) wsm[i] = rw[i];
    __syncthreads();

    const int idx = blockIdx.x * 256 + threadIdx.x;
    if (idx >= 128 * 2601) return;
    const int b = idx / 2601, px = idx - b * 2601;
    const int y = px / 51, x = px - y * 51;
    const float* hb = h2 + (size_t)b * 150 * 2401;

    float s = 0.f;
    for (int c = 0; c < 150; ++c) {
#pragma unroll
        for (int ky = 0; ky < 3; ++ky) {
            const int iy = y - 2 + ky;
            if (iy < 0 || iy >= 49) continue;
#pragma unroll
            for (int kx = 0; kx < 3; ++kx) {
                const int ix = x - 2 + kx;
                if (ix < 0 || ix >= 49) continue;
                s += __ldg(&hb[(c * 49 + iy) * 49 + ix]) * wsm[c * 9 + ky * 3 + kx];
            }
        }
    }
    rewout[idx] = s;
}

// ---------------- per-pixel softmax over k=9 within each of 8 actions (in place) ----------------
__global__ void softmax_kernel(float* __restrict__ t)
{
    const int idx = blockIdx.x * 256 + threadIdx.x;
    if (idx >= 128 * 2601) return;
    float* p = t + (size_t)idx * 72;
    float a_[72];
    float4* pv = reinterpret_cast<float4*>(p);
#pragma unroll
    for (int i = 0; i < 18; ++i) {
        float4 v = pv[i];
        a_[4 * i] = v.x; a_[4 * i + 1] = v.y; a_[4 * i + 2] = v.z; a_[4 * i + 3] = v.w;
    }
#pragma unroll
    for (int a = 0; a < 8; ++a) {
        const int bs = a * 9;
        float m = a_[bs];
#pragma unroll
        for (int k = 1; k < 9; ++k) m = fmaxf(m, a_[bs + k]);
        float s = 0.f;
#pragma unroll
        for (int k = 0; k < 9; ++k) { float e = expf(a_[bs + k] - m); a_[bs + k] = e; s += e; }
        const float inv = 1.f / s;
#pragma unroll
        for (int k = 0; k < 9; ++k) a_[bs + k] *= inv;
    }
#pragma unroll
    for (int i = 0; i < 18; ++i)
        pv[i] = make_float4(a_[4 * i], a_[4 * i + 1], a_[4 * i + 2], a_[4 * i + 3]);
}

// ---------------- value iteration: 1 CTA per batch, K=30, v in smem, sT in L2 ----------------
__global__ void vi_kernel(const float* __restrict__ sT, const float* __restrict__ rew,
                          float* __restrict__ qout)
{
    const int b = blockIdx.x;
    const int tid = threadIdx.x;
    __shared__ float vp[2][53 * 53];
    __shared__ float rs[2601];
    for (int i = tid; i < 53 * 53; i += 256) { vp[0][i] = 0.f; vp[1][i] = 0.f; }
    for (int i = tid; i < 2601; i += 256) rs[i] = rew[(size_t)b * 2601 + i];
    __syncthreads();

    const float* stb = sT + (size_t)b * 2601 * 72;
    int cur = 0;
    for (int it = 0; it < 30; ++it) {
        const bool last = (it == 29);
        for (int px = tid; px < 2601; px += 256) {
            const int y = px / 51, x = px - y * 51;
            const float* vc = &vp[cur][y * 53 + x];
            float vn[9];
#pragma unroll
            for (int ky = 0; ky < 3; ++ky)
#pragma unroll
                for (int kx = 0; kx < 3; ++kx) vn[ky * 3 + kx] = vc[ky * 53 + kx];

            float a_[72];
            const float4* sp = reinterpret_cast<const float4*>(stb + (size_t)px * 72);
#pragma unroll
            for (int i = 0; i < 18; ++i) {
                float4 v = __ldg(&sp[i]);
                a_[4 * i] = v.x; a_[4 * i + 1] = v.y; a_[4 * i + 2] = v.z; a_[4 * i + 3] = v.w;
            }
            const float r = rs[px];
            float vmax = -3.4e38f;
#pragma unroll
            for (int a = 0; a < 8; ++a) {
                float q = r;
#pragma unroll
                for (int k = 0; k < 9; ++k) q += a_[a * 9 + k] * vn[k];
                if (last && y < 49 && x < 49)
                    qout[(((size_t)b * 49 + y) * 49 + x) * 8 + a] = q;
                vmax = fmaxf(vmax, q);
            }
            vp[cur ^ 1][(y + 1) * 53 + (x + 1)] = vmax;
        }
        __syncthreads();
        cur ^= 1;
    }
}

// ---------------- head: per pixel 8 -> relu(150) -> 8, output (B,8,49,49) ----------------
__global__ void head_kernel(const float* __restrict__ q, const float* __restrict__ a1w,
                            const float* __restrict__ a1b, const float* __restrict__ a2w,
                            const float* __restrict__ a2b, float* __restrict__ out)
{
    __shared__ float s1[1200];   // a1_w[c][a]
    __shared__ float s2[1200];   // a2_w transposed -> [c][a]
    __shared__ float sb1[150];
    __shared__ float sb2[8];
    for (int i = threadIdx.x; i < 1200; i += 256) {
        s1[i] = a1w[i];
        const int c = i >> 3, a = i & 7;
        s2[i] = a2w[a * 150 + c];
    }
    for (int i = threadIdx.x; i < 150; i += 256) sb1[i] = a1b[i];
    if (threadIdx.x < 8) sb2[threadIdx.x] = a2b[threadIdx.x];
    __syncthreads();

    const int idx = blockIdx.x * 256 + threadIdx.x;
    if (idx >= 128 * 2401) return;
    const int b = idx / 2401, px = idx - b * 2401;

    const float4* qp = reinterpret_cast<const float4*>(q + (size_t)idx * 8);
    const float4 q0 = qp[0], q1 = qp[1];
    const float qv[8] = { q0.x, q0.y, q0.z, q0.w, q1.x, q1.y, q1.z, q1.w };

    float lg[8];
#pragma unroll
    for (int a = 0; a < 8; ++a) lg[a] = sb2[a];

    for (int c = 0; c < 150; ++c) {
        float m = sb1[c];
#pragma unroll
        for (int a = 0; a < 8; ++a) m += s1[c * 8 + a] * qv[a];
        m = fmaxf(m, 0.f);
#pragma unroll
        for (int a = 0; a < 8; ++a) lg[a] += s2[c * 8 + a] * m;
    }
    float* ob = out + (size_t)b * 8 * 2401 + px;
#pragma unroll
    for (int a = 0; a < 8; ++a) ob[(size_t)a * 2401] = lg[a];
}

// ---------------- launch ----------------
extern "C" void kernel_launch(void* const* d_in, const int* in_sizes, int n_in,
                              void* d_out, int out_size)
{
    const float* grid = (const float*)d_in[0];
    // d_in[1], d_in[2] = x_coord, y_coord: unused by the reference output
    const float* h1w = (const float*)d_in[3];
    const float* h1b = (const float*)d_in[4];
    const float* h2w = (const float*)d_in[5];
    const float* h2b = (const float*)d_in[6];
    const float* rw  = (const float*)d_in[7];
    const float* tw  = (const float*)d_in[8];
    const float* a1w = (const float*)d_in[9];
    const float* a1b = (const float*)d_in[10];
    const float* a2w = (const float*)d_in[11];
    const float* a2b = (const float*)d_in[12];
    float* out = (float*)d_out;

    float *h1, *h2, *sT, *rwb, *qb;
    cudaGetSymbolAddress((void**)&h1, g_h1);
    cudaGetSymbolAddress((void**)&h2, g_h2);
    cudaGetSymbolAddress((void**)&sT, g_sT);
    cudaGetSymbolAddress((void**)&rwb, g_rew);
    cudaGetSymbolAddress((void**)&qb, g_q);

    // conv1: 2->150, pad1, relu
    conv3x3_kernel<2, 1, true, 30, 6, 0><<<dim3(9, 5, 128), 210>>>(grid, h1w, h1b, h1, 150);
    // conv2: 150->150, pad1, relu
    conv3x3_kernel<150, 1, true, 30, 6, 0><<<dim3(9, 5, 128), 210>>>(h1, h2w, h2b, h2, 150);
    // trans: 150->72, pad2, no relu, pixel-major output
    conv3x3_kernel<150, 2, false, 24, 6, 1><<<dim3(9, 3, 128), 168>>>(h2, tw, nullptr, sT, 72);
    // reward: 150->1, pad2
    reward_kernel<<<(128 * 2601 + 255) / 256, 256>>>(h2, rw, rwb);
    // softmax over the 9 kernel taps per action (in place on sT)
    softmax_kernel<<<(128 * 2601 + 255) / 256, 256>>>(sT);
    // K=30 value iteration, persistent CTA per batch
    vi_kernel<<<128, 256>>>(sT, rwb, qb);
    // head 8->150->8
    head_kernel<<<(128 * 2401 + 255) / 256, 256>>>(qb, a1w, a1b, a2w, a2b, out);
}

// round 2
// speedup vs baseline: 2.3334x; 2.3334x over previous
#include <cuda_runtime.h>

// ---------------- scratch (device globals; no allocations allowed) ----------------
__device__ float g_h1[46099200];   // (128,150,49,49)
__device__ float g_h2[46099200];   // (128,150,49,49)
__device__ float g_sT[23970816];   // (128,51*51,72)  trans -> softmax in-place
__device__ float g_rew[332928];    // (128,51*51)
__device__ float g_q[2458624];     // (128,49,49,8)

__device__ __forceinline__ unsigned int f2tf32(float v) {
    unsigned int u;
    asm("cvt.rna.tf32.f32 %0, %1;" : "=r"(u) : "f"(v));
    return u;
}

__device__ __forceinline__ void mma_tf32(float* c, unsigned int a0, unsigned int a1,
                                         unsigned int a2, unsigned int a3,
                                         unsigned int b0, unsigned int b1) {
    asm volatile("mma.sync.aligned.m16n8k8.row.col.f32.tf32.tf32.f32 "
                 "{%0,%1,%2,%3}, {%4,%5,%6,%7}, {%8,%9}, {%0,%1,%2,%3};"
                 : "+f"(c[0]), "+f"(c[1]), "+f"(c[2]), "+f"(c[3])
                 : "r"(a0), "r"(a1), "r"(a2), "r"(a3), "r"(b0), "r"(b1));
}

// =================================================================================
// Implicit-GEMM 3x3 conv on tensor cores (tf32 mma.sync).
//  Input: (B, IC, 49, 49) NCHW fp32.  Output HW = 47+2*PAD (49 or 51).
//  GEMM: M = out-channels (80 per CTA, 5 warps x m16), N = 128 consecutive output
//  pixels (16 n8-tiles), K = IC*9 (ic-chunks of 8, 9 taps each).
//  EPI=0: NCHW out, +bias, optional relu.
//  EPI=1: pixel-major sT out (b, px, oc) for oc<72; oc==72 -> reward buffer.
// =================================================================================
template<int IC, int PAD, int EPI, bool RELU>
__global__ void __launch_bounds__(160)
conv_mma_kernel(const float* __restrict__ in, const float* __restrict__ w,
                const float* __restrict__ w2, const float* __restrict__ bias,
                float* __restrict__ out, float* __restrict__ rew, const int OC)
{
    constexpr int HW     = 47 + 2 * PAD;       // output size
    constexpr int NPX    = HW * HW;
    constexpr int CHUNKS = (IC + 7) / 8;
    constexpr int WX     = 56;                 // staged row width (cols 0..52 used)
    constexpr int XPLANE = 344;                // 6*56=336, padded to 344 (bank stagger)
    constexpr int WSTRIDE = 89;                // oc stride in Ws (bank stagger)

    __shared__ unsigned int Xs[8 * XPLANE];        // [ic_k][row 0..5][col] tf32
    __shared__ unsigned int Ws[9 * 8 * WSTRIDE];   // [tap][ic_k][oc] tf32

    const int tid  = threadIdx.x;
    const int lane = tid & 31;
    const int warp = tid >> 5;        // 0..4, m-tile index
    const int tig  = lane & 3;
    const int grp  = lane >> 2;

    const int n0  = blockIdx.x * 128;
    const int oc0 = blockIdx.y * 80;
    const int b   = blockIdx.z;
    const int ocw = warp * 16;        // warp oc base within CTA

    const int ybase = n0 / HW;
    const float* inb = in + (size_t)b * IC * 2401;

    // Precompute per-ntile B base offsets (row-in-tile * WX + col) — constant over K.
    int basent[16];
#pragma unroll
    for (int nt = 0; nt < 16; ++nt) {
        int n = n0 + nt * 8 + grp;
        if (n > NPX - 1) n = NPX - 1;
        const int y = n / HW, x = n - y * HW;
        basent[nt] = (y - ybase) * WX + x;
    }

    float c[16][4];
#pragma unroll
    for (int nt = 0; nt < 16; ++nt)
#pragma unroll
        for (int j = 0; j < 4; ++j) c[nt][j] = 0.f;

    for (int ch = 0; ch < CHUNKS; ++ch) {
        __syncthreads();
        const int ic0 = ch * 8;

        // ---- stage activations: rows (ybase-PAD)..(ybase-PAD+5), cols -PAD..  ----
        for (int i = tid; i < 8 * 6 * WX; i += 160) {
            const int k = i / (6 * WX);
            const int rem = i - k * (6 * WX);
            const int r = rem / WX, ccol = rem - r * WX;
            const int ic = ic0 + k;
            const int irow = ybase - PAD + r;
            const int icol = ccol - PAD;
            float v = 0.f;
            if (ic < IC && irow >= 0 && irow < 49 && icol >= 0 && icol < 49)
                v = inb[(ic * 49 + irow) * 49 + icol];
            Xs[k * XPLANE + r * WX + ccol] = f2tf32(v);
        }

        // ---- stage weights: [tap][k][oc], tap fastest in gmem read (coalesced) ----
        for (int i = tid; i < 9 * 8 * 80; i += 160) {
            const int tap = i % 9;
            const int k   = (i / 9) & 7;
            const int oc  = i / 72;
            const int ic  = ic0 + k;
            const int goc = oc0 + oc;
            float v = 0.f;
            if (ic < IC && goc < OC) {
                if (EPI == 1 && goc == 72)
                    v = w2[ic * 9 + tap];                  // reward weights (1,IC,3,3)
                else
                    v = w[((size_t)goc * IC + ic) * 9 + tap];
            }
            Ws[tap * (8 * WSTRIDE) + k * WSTRIDE + oc] = f2tf32(v);
        }
        __syncthreads();

#pragma unroll
        for (int tap = 0; tap < 9; ++tap) {
            const int ky = tap / 3, kx = tap - ky * 3;
            const int tapoff = ky * WX + kx;
            const unsigned int* wsb = &Ws[tap * (8 * WSTRIDE)];
            const unsigned int a0 = wsb[tig * WSTRIDE + ocw + grp];
            const unsigned int a1 = wsb[tig * WSTRIDE + ocw + grp + 8];
            const unsigned int a2 = wsb[(tig + 4) * WSTRIDE + ocw + grp];
            const unsigned int a3 = wsb[(tig + 4) * WSTRIDE + ocw + grp + 8];
#pragma unroll
            for (int nt = 0; nt < 16; ++nt) {
                const int boff = basent[nt] + tapoff;
                const unsigned int b0 = Xs[tig * XPLANE + boff];
                const unsigned int b1 = Xs[(tig + 4) * XPLANE + boff];
                mma_tf32(c[nt], a0, a1, a2, a3, b0, b1);
            }
        }
    }

    // ---------------- epilogue ----------------
    const int ocA = oc0 + ocw + grp;     // rows grp / grp+8
#pragma unroll
    for (int nt = 0; nt < 16; ++nt) {
#pragma unroll
        for (int j = 0; j < 4; ++j) {
            const int oc = ocA + ((j >= 2) ? 8 : 0);
            const int px = n0 + nt * 8 + tig * 2 + (j & 1);
            if (px >= NPX || oc >= OC) continue;
            float v = c[nt][j];
            if (EPI == 0) {
                v += bias[oc];
                if (RELU) v = fmaxf(v, 0.f);
                const int y = px / HW, x = px - y * HW;
                out[((size_t)(b * OC + oc) * HW + y) * HW + x] = v;
            } else {
                if (oc < 72)
                    out[((size_t)b * 2601 + px) * 72 + oc] = v;
                else if (oc == 72)
                    rew[(size_t)b * 2601 + px] = v;
            }
        }
    }
}

// ---------------- per-pixel softmax over k=9 within each of 8 actions (in place) ----------------
__global__ void softmax_kernel(float* __restrict__ t)
{
    const int idx = blockIdx.x * 256 + threadIdx.x;
    if (idx >= 128 * 2601) return;
    float* p = t + (size_t)idx * 72;
    float a_[72];
    float4* pv = reinterpret_cast<float4*>(p);
#pragma unroll
    for (int i = 0; i < 18; ++i) {
        float4 v = pv[i];
        a_[4 * i] = v.x; a_[4 * i + 1] = v.y; a_[4 * i + 2] = v.z; a_[4 * i + 3] = v.w;
    }
#pragma unroll
    for (int a = 0; a < 8; ++a) {
        const int bs = a * 9;
        float m = a_[bs];
#pragma unroll
        for (int k = 1; k < 9; ++k) m = fmaxf(m, a_[bs + k]);
        float s = 0.f;
#pragma unroll
        for (int k = 0; k < 9; ++k) { float e = expf(a_[bs + k] - m); a_[bs + k] = e; s += e; }
        const float inv = 1.f / s;
#pragma unroll
        for (int k = 0; k < 9; ++k) a_[bs + k] *= inv;
    }
#pragma unroll
    for (int i = 0; i < 18; ++i)
        pv[i] = make_float4(a_[4 * i], a_[4 * i + 1], a_[4 * i + 2], a_[4 * i + 3]);
}

// ---------------- value iteration: 1 CTA per batch, K=30, v in smem, sT in L2 ----------------
__global__ void vi_kernel(const float* __restrict__ sT, const float* __restrict__ rew,
                          float* __restrict__ qout)
{
    const int b = blockIdx.x;
    const int tid = threadIdx.x;
    __shared__ float vp[2][53 * 53];
    __shared__ float rs[2601];
    for (int i = tid; i < 53 * 53; i += 256) { vp[0][i] = 0.f; vp[1][i] = 0.f; }
    for (int i = tid; i < 2601; i += 256) rs[i] = rew[(size_t)b * 2601 + i];
    __syncthreads();

    const float* stb = sT + (size_t)b * 2601 * 72;
    int cur = 0;
    for (int it = 0; it < 30; ++it) {
        const bool last = (it == 29);
        for (int px = tid; px < 2601; px += 256) {
            const int y = px / 51, x = px - y * 51;
            const float* vc = &vp[cur][y * 53 + x];
            float vn[9];
#pragma unroll
            for (int ky = 0; ky < 3; ++ky)
#pragma unroll
                for (int kx = 0; kx < 3; ++kx) vn[ky * 3 + kx] = vc[ky * 53 + kx];

            float a_[72];
            const float4* sp = reinterpret_cast<const float4*>(stb + (size_t)px * 72);
#pragma unroll
            for (int i = 0; i < 18; ++i) {
                float4 v = __ldg(&sp[i]);
                a_[4 * i] = v.x; a_[4 * i + 1] = v.y; a_[4 * i + 2] = v.z; a_[4 * i + 3] = v.w;
            }
            const float r = rs[px];
            float vmax = -3.4e38f;
#pragma unroll
            for (int a = 0; a < 8; ++a) {
                float q = r;
#pragma unroll
                for (int k = 0; k < 9; ++k) q += a_[a * 9 + k] * vn[k];
                if (last && y < 49 && x < 49)
                    qout[(((size_t)b * 49 + y) * 49 + x) * 8 + a] = q;
                vmax = fmaxf(vmax, q);
            }
            vp[cur ^ 1][(y + 1) * 53 + (x + 1)] = vmax;
        }
        __syncthreads();
        cur ^= 1;
    }
}

// ---------------- head: per pixel 8 -> relu(150) -> 8, output (B,8,49,49) ----------------
__global__ void head_kernel(const float* __restrict__ q, const float* __restrict__ a1w,
                            const float* __restrict__ a1b, const float* __restrict__ a2w,
                            const float* __restrict__ a2b, float* __restrict__ out)
{
    __shared__ float s1[1200];   // a1_w[c][a]
    __shared__ float s2[1200];   // a2_w transposed -> [c][a]
    __shared__ float sb1[150];
    __shared__ float sb2[8];
    for (int i = threadIdx.x; i < 1200; i += 256) {
        s1[i] = a1w[i];
        const int c = i >> 3, a = i & 7;
        s2[i] = a2w[a * 150 + c];
    }
    for (int i = threadIdx.x; i < 150; i += 256) sb1[i] = a1b[i];
    if (threadIdx.x < 8) sb2[threadIdx.x] = a2b[threadIdx.x];
    __syncthreads();

    const int idx = blockIdx.x * 256 + threadIdx.x;
    if (idx >= 128 * 2401) return;
    const int b = idx / 2401, px = idx - b * 2401;

    const float4* qp = reinterpret_cast<const float4*>(q + (size_t)idx * 8);
    const float4 q0 = qp[0], q1 = qp[1];
    const float qv[8] = { q0.x, q0.y, q0.z, q0.w, q1.x, q1.y, q1.z, q1.w };

    float lg[8];
#pragma unroll
    for (int a = 0; a < 8; ++a) lg[a] = sb2[a];

    for (int c = 0; c < 150; ++c) {
        float m = sb1[c];
#pragma unroll
        for (int a = 0; a < 8; ++a) m += s1[c * 8 + a] * qv[a];
        m = fmaxf(m, 0.f);
#pragma unroll
        for (int a = 0; a < 8; ++a) lg[a] += s2[c * 8 + a] * m;
    }
    float* ob = out + (size_t)b * 8 * 2401 + px;
#pragma unroll
    for (int a = 0; a < 8; ++a) ob[(size_t)a * 2401] = lg[a];
}

// ---------------- launch ----------------
extern "C" void kernel_launch(void* const* d_in, const int* in_sizes, int n_in,
                              void* d_out, int out_size)
{
    const float* grid = (const float*)d_in[0];
    // d_in[1], d_in[2] = x_coord, y_coord: unused by the reference output
    const float* h1w = (const float*)d_in[3];
    const float* h1b = (const float*)d_in[4];
    const float* h2w = (const float*)d_in[5];
    const float* h2b = (const float*)d_in[6];
    const float* rw  = (const float*)d_in[7];
    const float* tw  = (const float*)d_in[8];
    const float* a1w = (const float*)d_in[9];
    const float* a1b = (const float*)d_in[10];
    const float* a2w = (const float*)d_in[11];
    const float* a2b = (const float*)d_in[12];
    float* out = (float*)d_out;

    float *h1, *h2, *sT, *rwb, *qb;
    cudaGetSymbolAddress((void**)&h1, g_h1);
    cudaGetSymbolAddress((void**)&h2, g_h2);
    cudaGetSymbolAddress((void**)&sT, g_sT);
    cudaGetSymbolAddress((void**)&rwb, g_rew);
    cudaGetSymbolAddress((void**)&qb, g_q);

    // conv1: 2->150, pad1, relu   (N: ceil(2401/128)=19 tiles, M: 2 x 80)
    conv_mma_kernel<2, 1, 0, true><<<dim3(19, 2, 128), 160>>>(grid, h1w, nullptr, h1b, h1, nullptr, 150);
    // conv2: 150->150, pad1, relu
    conv_mma_kernel<150, 1, 0, true><<<dim3(19, 2, 128), 160>>>(h1, h2w, nullptr, h2b, h2, nullptr, 150);
    // trans (oc 0..71) + reward (oc 72) fused: pad2, pixel-major sT output
    conv_mma_kernel<150, 2, 1, false><<<dim3(21, 1, 128), 160>>>(h2, tw, rw, nullptr, sT, rwb, 73);
    // softmax over the 9 kernel taps per action (in place on sT)
    softmax_kernel<<<(128 * 2601 + 255) / 256, 256>>>(sT);
    // K=30 value iteration, persistent CTA per batch
    vi_kernel<<<128, 256>>>(sT, rwb, qb);
    // head 8->150->8
    head_kernel<<<(128 * 2401 + 255) / 256, 256>>>(qb, a1w, a1b, a2w, a2b, out);
}

// round 6
// speedup vs baseline: 2.5138x; 1.0773x over previous
#include <cuda_runtime.h>
#include <cstdint>

// ---------------- scratch (device globals; no allocations allowed) ----------------
__device__ float g_h1[46099200];   // (128,150,49,49)
__device__ float g_h2[46099200];   // (128,150,49,49)
__device__ float g_sT[23970816];   // (128,51*51,72)  trans -> softmax in-place
__device__ float g_rew[332928];    // (128,51*51)
__device__ float g_q[2458624];     // (128,49,49,8)
__device__ float g_wp[360448];     // pre-permuted tf32 weights (conv1/conv2/trans)

__device__ __forceinline__ unsigned int f2tf32(float v) {
    unsigned int u;
    asm("cvt.rna.tf32.f32 %0, %1;" : "=r"(u) : "f"(v));
    return u;
}

__device__ __forceinline__ void mma_tf32(float* c, unsigned int a0, unsigned int a1,
                                         unsigned int a2, unsigned int a3,
                                         unsigned int b0, unsigned int b1) {
    asm volatile("mma.sync.aligned.m16n8k8.row.col.f32.tf32.tf32.f32 "
                 "{%0,%1,%2,%3}, {%4,%5,%6,%7}, {%8,%9}, {%0,%1,%2,%3};"
                 : "+f"(c[0]), "+f"(c[1]), "+f"(c[2]), "+f"(c[3])
                 : "r"(a0), "r"(a1), "r"(a2), "r"(a3), "r"(b0), "r"(b1));
}

// =================================================================================
// Weight pre-permutation: gmem -> fragment-ordered tf32 image.
// Flat layout: [ot][ch][tap][mt(5)][grp(8)][tig(4)][j(4)]
//   j=0:(oc=16mt+grp, ic=tig)  j=1:(oc+8, tig)  j=2:(oc, tig+4)  j=3:(oc+8, tig+4)
// epi: trans+reward fusion (oc 72 = reward weights, oc>72 = 0).
// =================================================================================
__global__ void prep_kernel(const float* __restrict__ w, const float* __restrict__ w2,
                            float* __restrict__ dst, int IC, int OC, int CH, int epi, int total)
{
    const int idx = blockIdx.x * 256 + threadIdx.x;
    if (idx >= total) return;
    const int j   = idx & 3;
    const int tig = (idx >> 2) & 3;
    const int grp = (idx >> 4) & 7;
    const int r1  = idx >> 7;
    const int mt  = r1 % 5;
    const int r2  = r1 / 5;
    const int tap = r2 % 9;
    const int r3  = r2 / 9;
    const int ch  = r3 % CH;
    const int ot  = r3 / CH;

    const int oc  = ot * 80 + mt * 16 + grp + (j & 1) * 8;
    const int ick = tig + (j >> 1) * 4;
    const int ic  = ch * 8 + ick;

    float v = 0.f;
    if (ic < IC) {
        if (epi) {
            if (oc == 72)      v = w2[ic * 9 + tap];
            else if (oc < 72)  v = w[((size_t)oc * IC + ic) * 9 + tap];
        } else if (oc < OC) {
            v = w[((size_t)oc * IC + ic) * 9 + tap];
        }
    }
    reinterpret_cast<unsigned int*>(dst)[idx] = f2tf32(v);
}

// =================================================================================
// Implicit-GEMM 3x3 conv, mma.sync tf32.  M=80 oc (5 warps x m16), N=128 px,
// K per chunk = 8 ic x 9 taps.  A fragments via 1 LDS.128/tap, B via 1 LDS.64/mma.
// XP2 row stride 338 float2 (2704B) -> tig groups offset by 4 banks (conflict-free).
// EPI=0: NCHW out (+bias, relu).  EPI=1: sT pixel-major; oc==72 -> reward.
// =================================================================================
template<int IC, int PAD, int EPI, bool RELU>
__global__ void __launch_bounds__(160, 2)
conv_mma2(const float* __restrict__ in, const float* __restrict__ wp,
          const float* __restrict__ bias, float* __restrict__ out,
          float* __restrict__ rew, const int OC)
{
    constexpr int HW  = 47 + 2 * PAD;
    constexpr int NPX = HW * HW;
    constexpr int CH  = (IC + 7) / 8;
    constexpr int XSTR = 338;                      // float2 row stride per tig-slot

    __shared__ float4 smem4[2692];                 // 10768 floats (~43KB)
    float* smem_all = reinterpret_cast<float*>(smem4);
    float2* XP2 = reinterpret_cast<float2*>(smem_all);           // acts: 4*338 float2 = 2704 f
    float*  APf = smem_all + 2704;                               // weights: 5760 floats
    const float4* AP4 = reinterpret_cast<const float4*>(APf);

    const int tid  = threadIdx.x;
    const int lane = tid & 31;
    const int warp = tid >> 5;          // 0..4 = m-tile
    const int tig  = lane & 3;
    const int grp  = lane >> 2;

    const int n0  = blockIdx.x * 128;
    const int ot  = blockIdx.y;
    const int oc0 = ot * 80;
    const int b   = blockIdx.z;
    const int ybase = n0 / HW;
    const float* inb = in + (size_t)b * IC * 2401;
    const float* wpc = wp + (size_t)ot * CH * 5760;

    // per-ntile B spatial base (row-in-tile*56 + col) for pixel nt*8+grp
    int basent[16];
#pragma unroll
    for (int nt = 0; nt < 16; ++nt) {
        int n = n0 + nt * 8 + grp;
        if (n > NPX - 1) n = NPX - 1;
        const int y = n / HW, x = n - y * HW;
        basent[nt] = (y - ybase) * 56 + x;
    }

    float c[16][4];
#pragma unroll
    for (int nt = 0; nt < 16; ++nt)
#pragma unroll
        for (int j = 0; j < 4; ++j) c[nt][j] = 0.f;

    for (int ch = 0; ch < CH; ++ch) {
        __syncthreads();
        // ---- stage A: straight float4 copy of pre-permuted weights ----
        {
            const float4* src = reinterpret_cast<const float4*>(wpc + (size_t)ch * 5760);
            float4* dst = reinterpret_cast<float4*>(APf);
            for (int i = tid; i < 1440; i += 160) dst[i] = src[i];
        }
        // ---- stage X: 8 ics x 6 rows x 56 cols, stored as (ic, ic+4) float2 pairs ----
        {
            const int ic0 = ch * 8;
            for (int i = tid; i < 2688; i += 160) {
                const int ick = i / 336;
                const int rem = i - ick * 336;
                const int r = rem / 56, cc = rem - r * 56;
                const int ic = ic0 + ick;
                const int iy = ybase - PAD + r;
                const int ix = cc - PAD;
                float v = 0.f;
                if (ic < IC && iy >= 0 && iy < 49 && ix >= 0 && ix < 49)
                    v = inb[ic * 2401 + iy * 49 + ix];
                reinterpret_cast<unsigned int*>(smem_all)[((ick & 3) * XSTR + rem) * 2 + (ick >> 2)] = f2tf32(v);
            }
        }
        __syncthreads();

        // ---- mma loop ----
#pragma unroll
        for (int tap = 0; tap < 9; ++tap) {
            const int ky = tap / 3, kx = tap - ky * 3;
            const int tapoff = ky * 56 + kx;
            const float4 a = AP4[((tap * 5 + warp) * 8 + grp) * 4 + tig];
            const unsigned int a0 = __float_as_uint(a.x);
            const unsigned int a1 = __float_as_uint(a.y);
            const unsigned int a2 = __float_as_uint(a.z);
            const unsigned int a3 = __float_as_uint(a.w);
            const float2* xb = XP2 + tig * XSTR + tapoff;
#pragma unroll
            for (int nt = 0; nt < 16; ++nt) {
                const float2 bv = xb[basent[nt]];
                mma_tf32(c[nt], a0, a1, a2, a3, __float_as_uint(bv.x), __float_as_uint(bv.y));
            }
        }
    }

    // ---- epilogue: regs -> smem transpose -> coalesced gmem ----
    __syncthreads();
#pragma unroll
    for (int nt = 0; nt < 16; ++nt)
#pragma unroll
        for (int j = 0; j < 4; ++j) {
            const int rl = warp * 16 + grp + 8 * (j >> 1);
            const int pl = nt * 8 + tig * 2 + (j & 1);
            if (EPI == 0) smem_all[rl * 132 + pl] = c[nt][j];
            else          smem_all[pl * 84 + rl] = c[nt][j];
        }
    __syncthreads();

    if (EPI == 0) {
        for (int i = tid; i < 80 * 128; i += 160) {
            const int ocl = i >> 7, px = i & 127;
            const int oc = oc0 + ocl, pg = n0 + px;
            if (oc < OC && pg < NPX) {
                float v = smem_all[ocl * 132 + px] + bias[oc];
                if (RELU) v = fmaxf(v, 0.f);
                out[(size_t)(b * OC + oc) * NPX + pg] = v;
            }
        }
    } else {
        for (int i = tid; i < 128 * 73; i += 160) {
            const int px = i / 73, ocl = i - px * 73;
            const int pg = n0 + px;
            if (pg < NPX) {
                const float v = smem_all[px * 84 + ocl];
                if (ocl < 72)       out[((size_t)b * 2601 + pg) * 72 + ocl] = v;
                else                rew[(size_t)b * 2601 + pg] = v;
            }
        }
    }
}

// ---------------- per-pixel softmax over k=9 within each of 8 actions (in place) ----------------
__global__ void softmax_kernel(float* __restrict__ t)
{
    const int idx = blockIdx.x * 256 + threadIdx.x;
    if (idx >= 128 * 2601) return;
    float* p = t + (size_t)idx * 72;
    float a_[72];
    float4* pv = reinterpret_cast<float4*>(p);
#pragma unroll
    for (int i = 0; i < 18; ++i) {
        float4 v = pv[i];
        a_[4 * i] = v.x; a_[4 * i + 1] = v.y; a_[4 * i + 2] = v.z; a_[4 * i + 3] = v.w;
    }
#pragma unroll
    for (int a = 0; a < 8; ++a) {
        const int bs = a * 9;
        float m = a_[bs];
#pragma unroll
        for (int k = 1; k < 9; ++k) m = fmaxf(m, a_[bs + k]);
        float s = 0.f;
#pragma unroll
        for (int k = 0; k < 9; ++k) { float e = expf(a_[bs + k] - m); a_[bs + k] = e; s += e; }
        const float inv = 1.f / s;
#pragma unroll
        for (int k = 0; k < 9; ++k) a_[bs + k] *= inv;
    }
#pragma unroll
    for (int i = 0; i < 18; ++i)
        pv[i] = make_float4(a_[4 * i], a_[4 * i + 1], a_[4 * i + 2], a_[4 * i + 3]);
}

// ---------------- value iteration: 1 CTA per batch, K=30, v in smem, sT in L2 ----------------
__global__ void vi_kernel(const float* __restrict__ sT, const float* __restrict__ rew,
                          float* __restrict__ qout)
{
    const int b = blockIdx.x;
    const int tid = threadIdx.x;
    __shared__ float vp[2][53 * 53];
    __shared__ float rs[2601];
    for (int i = tid; i < 53 * 53; i += 256) { vp[0][i] = 0.f; vp[1][i] = 0.f; }
    for (int i = tid; i < 2601; i += 256) rs[i] = rew[(size_t)b * 2601 + i];
    __syncthreads();

    const float* stb = sT + (size_t)b * 2601 * 72;
    int cur = 0;
    for (int it = 0; it < 30; ++it) {
        const bool last = (it == 29);
        for (int px = tid; px < 2601; px += 256) {
            const int y = px / 51, x = px - y * 51;
            const float* vc = &vp[cur][y * 53 + x];
            float vn[9];
#pragma unroll
            for (int ky = 0; ky < 3; ++ky)
#pragma unroll
                for (int kx = 0; kx < 3; ++kx) vn[ky * 3 + kx] = vc[ky * 53 + kx];

            float a_[72];
            const float4* sp = reinterpret_cast<const float4*>(stb + (size_t)px * 72);
#pragma unroll
            for (int i = 0; i < 18; ++i) {
                float4 v = __ldg(&sp[i]);
                a_[4 * i] = v.x; a_[4 * i + 1] = v.y; a_[4 * i + 2] = v.z; a_[4 * i + 3] = v.w;
            }
            const float r = rs[px];
            float vmax = -3.4e38f;
#pragma unroll
            for (int a = 0; a < 8; ++a) {
                float q = r;
#pragma unroll
                for (int k = 0; k < 9; ++k) q += a_[a * 9 + k] * vn[k];
                if (last && y < 49 && x < 49)
                    qout[(((size_t)b * 49 + y) * 49 + x) * 8 + a] = q;
                vmax = fmaxf(vmax, q);
            }
            vp[cur ^ 1][(y + 1) * 53 + (x + 1)] = vmax;
        }
        __syncthreads();
        cur ^= 1;
    }
}

// ---------------- head: per pixel 8 -> relu(150) -> 8, output (B,8,49,49) ----------------
__global__ void head_kernel(const float* __restrict__ q, const float* __restrict__ a1w,
                            const float* __restrict__ a1b, const float* __restrict__ a2w,
                            const float* __restrict__ a2b, float* __restrict__ out)
{
    __shared__ float s1[1200];
    __shared__ float s2[1200];
    __shared__ float sb1[150];
    __shared__ float sb2[8];
    for (int i = threadIdx.x; i < 1200; i += 256) {
        s1[i] = a1w[i];
        const int c = i >> 3, a = i & 7;
        s2[i] = a2w[a * 150 + c];
    }
    for (int i = threadIdx.x; i < 150; i += 256) sb1[i] = a1b[i];
    if (threadIdx.x < 8) sb2[threadIdx.x] = a2b[threadIdx.x];
    __syncthreads();

    const int idx = blockIdx.x * 256 + threadIdx.x;
    if (idx >= 128 * 2401) return;
    const int b = idx / 2401, px = idx - b * 2401;

    const float4* qp = reinterpret_cast<const float4*>(q + (size_t)idx * 8);
    const float4 q0 = qp[0], q1 = qp[1];
    const float qv[8] = { q0.x, q0.y, q0.z, q0.w, q1.x, q1.y, q1.z, q1.w };

    float lg[8];
#pragma unroll
    for (int a = 0; a < 8; ++a) lg[a] = sb2[a];

    for (int c = 0; c < 150; ++c) {
        float m = sb1[c];
#pragma unroll
        for (int a = 0; a < 8; ++a) m += s1[c * 8 + a] * qv[a];
        m = fmaxf(m, 0.f);
#pragma unroll
        for (int a = 0; a < 8; ++a) lg[a] += s2[c * 8 + a] * m;
    }
    float* ob = out + (size_t)b * 8 * 2401 + px;
#pragma unroll
    for (int a = 0; a < 8; ++a) ob[(size_t)a * 2401] = lg[a];
}

// ---------------- launch ----------------
extern "C" void kernel_launch(void* const* d_in, const int* in_sizes, int n_in,
                              void* d_out, int out_size)
{
    const float* grid = (const float*)d_in[0];
    const float* h1w = (const float*)d_in[3];
    const float* h1b = (const float*)d_in[4];
    const float* h2w = (const float*)d_in[5];
    const float* h2b = (const float*)d_in[6];
    const float* rw  = (const float*)d_in[7];
    const float* tw  = (const float*)d_in[8];
    const float* a1w = (const float*)d_in[9];
    const float* a1b = (const float*)d_in[10];
    const float* a2w = (const float*)d_in[11];
    const float* a2b = (const float*)d_in[12];
    float* out = (float*)d_out;

    float *h1, *h2, *sT, *rwb, *qb, *wp;
    cudaGetSymbolAddress((void**)&h1, g_h1);
    cudaGetSymbolAddress((void**)&h2, g_h2);
    cudaGetSymbolAddress((void**)&sT, g_sT);
    cudaGetSymbolAddress((void**)&rwb, g_rew);
    cudaGetSymbolAddress((void**)&qb, g_q);
    cudaGetSymbolAddress((void**)&wp, g_wp);

    // Pre-permute weights into fragment order (tf32).
    // conv1: ot=2, CH=1 -> 11520 ; conv2: ot=2, CH=19 -> 218880 ; trans: ot=1, CH=19 -> 109440
    prep_kernel<<<(11520 + 255) / 256, 256>>>(h1w, nullptr, wp, 2, 150, 1, 0, 11520);
    prep_kernel<<<(218880 + 255) / 256, 256>>>(h2w, nullptr, wp + 11520, 150, 150, 19, 0, 218880);
    prep_kernel<<<(109440 + 255) / 256, 256>>>(tw, rw, wp + 230400, 150, 73, 19, 1, 109440);

    // conv1: 2->150, pad1, relu
    conv_mma2<2, 1, 0, true><<<dim3(19, 2, 128), 160>>>(grid, wp, h1b, h1, nullptr, 150);
    // conv2: 150->150, pad1, relu
    conv_mma2<150, 1, 0, true><<<dim3(19, 2, 128), 160>>>(h1, wp + 11520, h2b, h2, nullptr, 150);
    // trans (oc 0..71) + reward (oc 72) fused: pad2, pixel-major sT output
    conv_mma2<150, 2, 1, false><<<dim3(21, 1, 128), 160>>>(h2, wp + 230400, nullptr, sT, rwb, 73);
    // softmax over the 9 kernel taps per action (in place on sT)
    softmax_kernel<<<(128 * 2601 + 255) / 256, 256>>>(sT);
    // K=30 value iteration, persistent CTA per batch
    vi_kernel<<<128, 256>>>(sT, rwb, qb);
    // head 8->150->8
    head_kernel<<<(128 * 2401 + 255) / 256, 256>>>(qb, a1w, a1b, a2w, a2b, out);
}

// round 11
// speedup vs baseline: 3.2522x; 1.2937x over previous
#include <cuda_runtime.h>
#include <cstdint>

// ---------------- scratch (device globals; no allocations allowed) ----------------
__device__ float g_h1[46099200];   // (128,150,49,49)
__device__ float g_h2[46099200];   // (128,150,49,49)
__device__ float g_sT[23970816];   // (128,51*51,72)  trans -> softmax in-place
__device__ float g_rew[332928];    // (128,51*51)
__device__ float g_q[2458624];     // (128,49,49,8)
__device__ float g_wp[360448];     // pre-permuted tf32 weights (conv1/conv2/trans)

__device__ __forceinline__ unsigned int f2tf32(float v) {
    unsigned int u;
    asm("cvt.rna.tf32.f32 %0, %1;" : "=r"(u) : "f"(v));
    return u;
}

__device__ __forceinline__ void mma_tf32(float* c, unsigned int a0, unsigned int a1,
                                         unsigned int a2, unsigned int a3,
                                         unsigned int b0, unsigned int b1) {
    asm volatile("mma.sync.aligned.m16n8k8.row.col.f32.tf32.tf32.f32 "
                 "{%0,%1,%2,%3}, {%4,%5,%6,%7}, {%8,%9}, {%0,%1,%2,%3};"
                 : "+f"(c[0]), "+f"(c[1]), "+f"(c[2]), "+f"(c[3])
                 : "r"(a0), "r"(a1), "r"(a2), "r"(a3), "r"(b0), "r"(b1));
}

// =================================================================================
// Weight pre-permutation: gmem -> fragment-ordered tf32 image.
// Flat layout: [ot][ch][tap][mt(5)][grp(8)][tig(4)][j(4)]
//   j=0:(oc=16mt+grp, ic=tig)  j=1:(oc+8, tig)  j=2:(oc, tig+4)  j=3:(oc+8, tig+4)
// epi: trans+reward fusion (oc 72 = reward weights, oc>72 = 0).
// =================================================================================
__global__ void prep_kernel(const float* __restrict__ w, const float* __restrict__ w2,
                            float* __restrict__ dst, int IC, int OC, int CH, int epi, int total)
{
    const int idx = blockIdx.x * 256 + threadIdx.x;
    if (idx >= total) return;
    const int j   = idx & 3;
    const int tig = (idx >> 2) & 3;
    const int grp = (idx >> 4) & 7;
    const int r1  = idx >> 7;
    const int mt  = r1 % 5;
    const int r2  = r1 / 5;
    const int tap = r2 % 9;
    const int r3  = r2 / 9;
    const int ch  = r3 % CH;
    const int ot  = r3 / CH;

    const int oc  = ot * 80 + mt * 16 + grp + (j & 1) * 8;
    const int ick = tig + (j >> 1) * 4;
    const int ic  = ch * 8 + ick;

    float v = 0.f;
    if (ic < IC) {
        if (epi) {
            if (oc == 72)      v = w2[ic * 9 + tap];
            else if (oc < 72)  v = w[((size_t)oc * IC + ic) * 9 + tap];
        } else if (oc < OC) {
            v = w[((size_t)oc * IC + ic) * 9 + tap];
        }
    }
    reinterpret_cast<unsigned int*>(dst)[idx] = f2tf32(v);
}

// =================================================================================
// Implicit-GEMM 3x3 conv, mma.sync tf32.  320 threads = 10 warps:
//   warp = (mt 0..4) x (n-half 0..1); each warp m16 x n64 -> c[8][4] (32 regs).
// K per chunk = 8 ic x 9 taps.  A fragments 1 LDS.128/tap, B 1 LDS.64/mma.
// Staging coords hoisted: per-thread slot list computed once, reused every chunk.
// EPI=0: NCHW out (+bias, relu).  EPI=1: sT pixel-major; oc==72 -> reward.
// =================================================================================
template<int IC, int PAD, int EPI, bool RELU>
__global__ void __launch_bounds__(320, 2)
conv_mma2(const float* __restrict__ in, const float* __restrict__ wp,
          const float* __restrict__ bias, float* __restrict__ out,
          float* __restrict__ rew, const int OC)
{
    constexpr int HW  = 47 + 2 * PAD;
    constexpr int NPX = HW * HW;
    constexpr int CH  = (IC + 7) / 8;
    constexpr int XSTR = 338;                      // float2 row stride per tig-slot
    constexpr int NSLOT = 9;                       // ceil(2688/320)

    __shared__ float4 smem4[2692];                 // 10768 floats (~43KB)
    float* smem_all = reinterpret_cast<float*>(smem4);
    float2* XP2 = reinterpret_cast<float2*>(smem_all);           // acts: 4*338 float2
    float*  APf = smem_all + 2704;                               // weights: 5760 floats
    const float4* AP4 = reinterpret_cast<const float4*>(APf);

    const int tid  = threadIdx.x;
    const int lane = tid & 31;
    const int warp = tid >> 5;          // 0..9
    const int mt   = warp >> 1;         // m-tile 0..4
    const int nh   = warp & 1;          // n-half 0..1
    const int tig  = lane & 3;
    const int grp  = lane >> 2;

    const int n0  = blockIdx.x * 128;
    const int ot  = blockIdx.y;
    const int oc0 = ot * 80;
    const int b   = blockIdx.z;
    const int ybase = n0 / HW;
    const float* inb = in + (size_t)b * IC * 2401;
    const float* wpc = wp + (size_t)ot * CH * 5760;

    // ---- hoisted staging slots: thread handles elements tid, tid+320, ... of 2688 ----
    uint32_t smoff[NSLOT];
    int      goff [NSLOT];
    int      icks [NSLOT];
    uint32_t vmask = 0;
#pragma unroll
    for (int s = 0; s < NSLOT; ++s) {
        const int e = tid + s * 320;
        smoff[s] = 0; goff[s] = 0; icks[s] = 0;
        if (e < 2688) {
            const int ick = e / 336;
            const int rem = e - ick * 336;
            const int r  = rem / 56;
            const int cc = rem - r * 56;
            const int iy = ybase - PAD + r;
            const int ix = cc - PAD;
            smoff[s] = (((uint32_t)(ick & 3) * XSTR + rem) << 1) + (ick >> 2);
            icks[s]  = ick;
            if (iy >= 0 && iy < 49 && ix >= 0 && ix < 49) {
                goff[s] = ick * 2401 + iy * 49 + ix;
                vmask |= (1u << s);
            }
        }
    }

    // per-ntile B spatial base for this warp's n-half (pixel (nh*8+nt)*8+grp)
    int basent[8];
#pragma unroll
    for (int nt = 0; nt < 8; ++nt) {
        int n = n0 + (nh * 8 + nt) * 8 + grp;
        if (n > NPX - 1) n = NPX - 1;
        const int y = n / HW, x = n - y * HW;
        basent[nt] = (y - ybase) * 56 + x;
    }

    float c[8][4];
#pragma unroll
    for (int nt = 0; nt < 8; ++nt)
#pragma unroll
        for (int j = 0; j < 4; ++j) c[nt][j] = 0.f;

    unsigned int* smem_u = reinterpret_cast<unsigned int*>(smem_all);

    for (int ch = 0; ch < CH; ++ch) {
        __syncthreads();
        // ---- stage A: straight float4 copy of pre-permuted weights ----
        {
            const float4* src = reinterpret_cast<const float4*>(wpc + (size_t)ch * 5760);
            float4* dst = reinterpret_cast<float4*>(APf);
            for (int i = tid; i < 1440; i += 320) dst[i] = src[i];
        }
        // ---- stage X via precomputed slots ----
        {
            const float* src = inb + ch * 8 * 2401;
            const int icbase = ch * 8;
#pragma unroll
            for (int s = 0; s < NSLOT; ++s) {
                const bool ok = ((vmask >> s) & 1u) && (icbase + icks[s] < IC);
                const float v = ok ? __ldg(src + goff[s]) : 0.f;
                if (tid + s * 320 < 2688) smem_u[smoff[s]] = f2tf32(v);
            }
        }
        __syncthreads();

        // ---- mma loop ----
#pragma unroll
        for (int tap = 0; tap < 9; ++tap) {
            const int ky = tap / 3, kx = tap - ky * 3;
            const int tapoff = ky * 56 + kx;
            const float4 a = AP4[((tap * 5 + mt) * 8 + grp) * 4 + tig];
            const unsigned int a0 = __float_as_uint(a.x);
            const unsigned int a1 = __float_as_uint(a.y);
            const unsigned int a2 = __float_as_uint(a.z);
            const unsigned int a3 = __float_as_uint(a.w);
            const float2* xb = XP2 + tig * XSTR + tapoff;
#pragma unroll
            for (int nt = 0; nt < 8; ++nt) {
                const float2 bv = xb[basent[nt]];
                mma_tf32(c[nt], a0, a1, a2, a3, __float_as_uint(bv.x), __float_as_uint(bv.y));
            }
        }
    }

    // ---- epilogue: regs -> smem transpose -> coalesced gmem ----
    __syncthreads();
#pragma unroll
    for (int nt = 0; nt < 8; ++nt)
#pragma unroll
        for (int j = 0; j < 4; ++j) {
            const int rl = mt * 16 + grp + 8 * (j >> 1);
            const int pl = (nh * 8 + nt) * 8 + tig * 2 + (j & 1);
            if (EPI == 0) smem_all[rl * 132 + pl] = c[nt][j];
            else          smem_all[pl * 84 + rl] = c[nt][j];
        }
    __syncthreads();

    if (EPI == 0) {
        for (int i = tid; i < 80 * 128; i += 320) {
            const int ocl = i >> 7, px = i & 127;
            const int oc = oc0 + ocl, pg = n0 + px;
            if (oc < OC && pg < NPX) {
                float v = smem_all[ocl * 132 + px] + bias[oc];
                if (RELU) v = fmaxf(v, 0.f);
                out[(size_t)(b * OC + oc) * NPX + pg] = v;
            }
        }
    } else {
        for (int i = tid; i < 128 * 73; i += 320) {
            const int px = i / 73, ocl = i - px * 73;
            const int pg = n0 + px;
            if (pg < NPX) {
                const float v = smem_all[px * 84 + ocl];
                if (ocl < 72)       out[((size_t)b * 2601 + pg) * 72 + ocl] = v;
                else                rew[(size_t)b * 2601 + pg] = v;
            }
        }
    }
}

// ---------------- per-pixel softmax over k=9 within each of 8 actions (in place) ----------------
__global__ void softmax_kernel(float* __restrict__ t)
{
    const int idx = blockIdx.x * 256 + threadIdx.x;
    if (idx >= 128 * 2601) return;
    float* p = t + (size_t)idx * 72;
    float a_[72];
    float4* pv = reinterpret_cast<float4*>(p);
#pragma unroll
    for (int i = 0; i < 18; ++i) {
        float4 v = pv[i];
        a_[4 * i] = v.x; a_[4 * i + 1] = v.y; a_[4 * i + 2] = v.z; a_[4 * i + 3] = v.w;
    }
#pragma unroll
    for (int a = 0; a < 8; ++a) {
        const int bs = a * 9;
        float m = a_[bs];
#pragma unroll
        for (int k = 1; k < 9; ++k) m = fmaxf(m, a_[bs + k]);
        float s = 0.f;
#pragma unroll
        for (int k = 0; k < 9; ++k) { float e = expf(a_[bs + k] - m); a_[bs + k] = e; s += e; }
        const float inv = 1.f / s;
#pragma unroll
        for (int k = 0; k < 9; ++k) a_[bs + k] *= inv;
    }
#pragma unroll
    for (int i = 0; i < 18; ++i)
        pv[i] = make_float4(a_[4 * i], a_[4 * i + 1], a_[4 * i + 2], a_[4 * i + 3]);
}

// ---------------- value iteration: 1 CTA per batch, K=30, v in smem, sT in L2 ----------------
// 512 threads: halves the per-thread px sweep depth (latency-bound on sT L2 loads).
__global__ void __launch_bounds__(512)
vi_kernel(const float* __restrict__ sT, const float* __restrict__ rew,
          float* __restrict__ qout)
{
    const int b = blockIdx.x;
    const int tid = threadIdx.x;
    __shared__ float vp[2][53 * 53];
    __shared__ float rs[2601];
    for (int i = tid; i < 53 * 53; i += 512) { vp[0][i] = 0.f; vp[1][i] = 0.f; }
    for (int i = tid; i < 2601; i += 512) rs[i] = rew[(size_t)b * 2601 + i];
    __syncthreads();

    const float* stb = sT + (size_t)b * 2601 * 72;
    int cur = 0;
    for (int it = 0; it < 30; ++it) {
        const bool last = (it == 29);
        for (int px = tid; px < 2601; px += 512) {
            const int y = px / 51, x = px - y * 51;
            const float* vc = &vp[cur][y * 53 + x];
            float vn[9];
#pragma unroll
            for (int ky = 0; ky < 3; ++ky)
#pragma unroll
                for (int kx = 0; kx < 3; ++kx) vn[ky * 3 + kx] = vc[ky * 53 + kx];

            float a_[72];
            const float4* sp = reinterpret_cast<const float4*>(stb + (size_t)px * 72);
#pragma unroll
            for (int i = 0; i < 18; ++i) {
                float4 v = __ldg(&sp[i]);
                a_[4 * i] = v.x; a_[4 * i + 1] = v.y; a_[4 * i + 2] = v.z; a_[4 * i + 3] = v.w;
            }
            const float r = rs[px];
            float vmax = -3.4e38f;
#pragma unroll
            for (int a = 0; a < 8; ++a) {
                float q = r;
#pragma unroll
                for (int k = 0; k < 9; ++k) q += a_[a * 9 + k] * vn[k];
                if (last && y < 49 && x < 49)
                    qout[(((size_t)b * 49 + y) * 49 + x) * 8 + a] = q;
                vmax = fmaxf(vmax, q);
            }
            vp[cur ^ 1][(y + 1) * 53 + (x + 1)] = vmax;
        }
        __syncthreads();
        cur ^= 1;
    }
}

// ---------------- head: per pixel 8 -> relu(150) -> 8, output (B,8,49,49) ----------------
__global__ void head_kernel(const float* __restrict__ q, const float* __restrict__ a1w,
                            const float* __restrict__ a1b, const float* __restrict__ a2w,
                            const float* __restrict__ a2b, float* __restrict__ out)
{
    __shared__ float s1[1200];
    __shared__ float s2[1200];
    __shared__ float sb1[150];
    __shared__ float sb2[8];
    for (int i = threadIdx.x; i < 1200; i += 256) {
        s1[i] = a1w[i];
        const int c = i >> 3, a = i & 7;
        s2[i] = a2w[a * 150 + c];
    }
    for (int i = threadIdx.x; i < 150; i += 256) sb1[i] = a1b[i];
    if (threadIdx.x < 8) sb2[threadIdx.x] = a2b[threadIdx.x];
    __syncthreads();

    const int idx = blockIdx.x * 256 + threadIdx.x;
    if (idx >= 128 * 2401) return;
    const int b = idx / 2401, px = idx - b * 2401;

    const float4* qp = reinterpret_cast<const float4*>(q + (size_t)idx * 8);
    const float4 q0 = qp[0], q1 = qp[1];
    const float qv[8] = { q0.x, q0.y, q0.z, q0.w, q1.x, q1.y, q1.z, q1.w };

    float lg[8];
#pragma unroll
    for (int a = 0; a < 8; ++a) lg[a] = sb2[a];

    for (int c = 0; c < 150; ++c) {
        float m = sb1[c];
#pragma unroll
        for (int a = 0; a < 8; ++a) m += s1[c * 8 + a] * qv[a];
        m = fmaxf(m, 0.f);
#pragma unroll
        for (int a = 0; a < 8; ++a) lg[a] += s2[c * 8 + a] * m;
    }
    float* ob = out + (size_t)b * 8 * 2401 + px;
#pragma unroll
    for (int a = 0; a < 8; ++a) ob[(size_t)a * 2401] = lg[a];
}

// ---------------- launch ----------------
extern "C" void kernel_launch(void* const* d_in, const int* in_sizes, int n_in,
                              void* d_out, int out_size)
{
    const float* grid = (const float*)d_in[0];
    const float* h1w = (const float*)d_in[3];
    const float* h1b = (const float*)d_in[4];
    const float* h2w = (const float*)d_in[5];
    const float* h2b = (const float*)d_in[6];
    const float* rw  = (const float*)d_in[7];
    const float* tw  = (const float*)d_in[8];
    const float* a1w = (const float*)d_in[9];
    const float* a1b = (const float*)d_in[10];
    const float* a2w = (const float*)d_in[11];
    const float* a2b = (const float*)d_in[12];
    float* out = (float*)d_out;

    float *h1, *h2, *sT, *rwb, *qb, *wp;
    cudaGetSymbolAddress((void**)&h1, g_h1);
    cudaGetSymbolAddress((void**)&h2, g_h2);
    cudaGetSymbolAddress((void**)&sT, g_sT);
    cudaGetSymbolAddress((void**)&rwb, g_rew);
    cudaGetSymbolAddress((void**)&qb, g_q);
    cudaGetSymbolAddress((void**)&wp, g_wp);

    // Pre-permute weights into fragment order (tf32).
    prep_kernel<<<(11520 + 255) / 256, 256>>>(h1w, nullptr, wp, 2, 150, 1, 0, 11520);
    prep_kernel<<<(218880 + 255) / 256, 256>>>(h2w, nullptr, wp + 11520, 150, 150, 19, 0, 218880);
    prep_kernel<<<(109440 + 255) / 256, 256>>>(tw, rw, wp + 230400, 150, 73, 19, 1, 109440);

    // conv1: 2->150, pad1, relu
    conv_mma2<2, 1, 0, true><<<dim3(19, 2, 128), 320>>>(grid, wp, h1b, h1, nullptr, 150);
    // conv2: 150->150, pad1, relu
    conv_mma2<150, 1, 0, true><<<dim3(19, 2, 128), 320>>>(h1, wp + 11520, h2b, h2, nullptr, 150);
    // trans (oc 0..71) + reward (oc 72) fused: pad2, pixel-major sT output
    conv_mma2<150, 2, 1, false><<<dim3(21, 1, 128), 320>>>(h2, wp + 230400, nullptr, sT, rwb, 73);
    // softmax over the 9 kernel taps per action (in place on sT)
    softmax_kernel<<<(128 * 2601 + 255) / 256, 256>>>(sT);
    // K=30 value iteration, persistent CTA per batch (512 threads)
    vi_kernel<<<128, 512>>>(sT, rwb, qb);
    // head 8->150->8
    head_kernel<<<(128 * 2401 + 255) / 256, 256>>>(qb, a1w, a1b, a2w, a2b, out);
}